// round 1
// baseline (speedup 1.0000x reference)
#include <cuda_runtime.h>
#include <math.h>

#define NN 384
#define CIN 128
#define DH 32
#define NH 4
#define M_TOT (NN*NN)   // 147456

// ---------------- scratch (no allocations allowed) ----------------
__device__ float g_xn[(size_t)M_TOT*CIN];      // layernormed x, [m][c]
__device__ float g_triBT[(size_t)NH*M_TOT];    // triangle bias TRANSPOSED: [h][k][q]
__device__ float g_Q[(size_t)M_TOT*CIN];       // [i][h][j][d]
__device__ float g_K[(size_t)M_TOT*CIN];
__device__ float g_V[(size_t)M_TOT*CIN];
__device__ float g_G[(size_t)M_TOT*CIN];       // sigmoid gate, [i][h][j][d]
__device__ float g_OG[(size_t)M_TOT*CIN];      // gated attention out, [m][h*32+d]
__device__ float g_Bqkvg[CIN*512];             // packed weights [k][n], n = h*128 + {q,k,v,g}*32 + d
__device__ float g_Bout[CIN*CIN];              // wo transposed [k][c]

// ---------------- K0: pack weights ----------------
__global__ void pack_kernel(const float* __restrict__ wq, const float* __restrict__ wk,
                            const float* __restrict__ wv, const float* __restrict__ wg,
                            const float* __restrict__ wo) {
    int idx = blockIdx.x * 256 + threadIdx.x;
    if (idx < CIN * 512) {
        int k = idx >> 9, n = idx & 511;
        int h = n >> 7, t = n & 127, sub = t >> 5, d = t & 31;
        const float* w = (sub == 0) ? wq : (sub == 1) ? wk : (sub == 2) ? wv : wg;
        float val = w[(h * DH + d) * CIN + k];
        if (sub == 0) val *= 0.17677669529663687f;   // 1/sqrt(32)
        g_Bqkvg[idx] = val;
    }
    if (idx < CIN * CIN) {
        int k = idx >> 7, c = idx & 127;
        g_Bout[idx] = wo[c * CIN + k];
    }
}

// ---------------- K1: LayerNorm + triangle bias ----------------
__global__ void __launch_bounds__(256) ln_kernel(const float* __restrict__ x,
                                                 const float* __restrict__ gamma,
                                                 const float* __restrict__ beta,
                                                 const float* __restrict__ wbias) {
    int wid = threadIdx.x >> 5, lane = threadIdx.x & 31;
    int p = blockIdx.x * 8 + wid;                 // position index, 147456 total
    const float4 v = ((const float4*)(x + (size_t)p * CIN))[lane];
    float s  = v.x + v.y + v.z + v.w;
    float sq = v.x*v.x + v.y*v.y + v.z*v.z + v.w*v.w;
    #pragma unroll
    for (int o = 16; o; o >>= 1) {
        s  += __shfl_xor_sync(~0u, s,  o);
        sq += __shfl_xor_sync(~0u, sq, o);
    }
    float mu   = s * (1.f / 128.f);
    float var  = sq * (1.f / 128.f) - mu * mu;
    float rstd = rsqrtf(var + 1e-5f);
    float4 g4 = ((const float4*)gamma)[lane];
    float4 b4 = ((const float4*)beta)[lane];
    float4 xn;
    xn.x = (v.x - mu) * rstd * g4.x + b4.x;
    xn.y = (v.y - mu) * rstd * g4.y + b4.y;
    xn.z = (v.z - mu) * rstd * g4.z + b4.z;
    xn.w = (v.w - mu) * rstd * g4.w + b4.w;
    ((float4*)(g_xn + (size_t)p * CIN))[lane] = xn;

    int i = p / NN, j = p - i * NN;
    #pragma unroll
    for (int h = 0; h < NH; h++) {
        float4 w4 = ((const float4*)(wbias + h * CIN))[lane];
        float d = xn.x*w4.x + xn.y*w4.y + xn.z*w4.z + xn.w*w4.w;
        #pragma unroll
        for (int o = 16; o; o >>= 1) d += __shfl_xor_sync(~0u, d, o);
        if (lane == 0) g_triBT[(size_t)h * M_TOT + j * NN + i] = d;  // [h][k=j][q=i]
    }
}

// ---------------- K2: projection GEMM (q,k,v,g for one head per block.y) ----------------
__global__ void __launch_bounds__(256, 1) proj_kernel(const float* __restrict__ bg) {
    extern __shared__ float sm[];
    float* As = sm;                 // [128][128]
    float* Bs = sm + 128 * 128;     // [128][128]
    int tid = threadIdx.x;
    int m0  = blockIdx.x * 128;
    int h   = blockIdx.y;

    const float4* Ag  = (const float4*)(g_xn + (size_t)m0 * CIN);
    const float4* Bg  = (const float4*)g_Bqkvg;
    float4* As4 = (float4*)As;
    float4* Bs4 = (float4*)Bs;
    #pragma unroll
    for (int r = 0; r < 16; r++) {
        int f = tid + r * 256;
        As4[f] = Ag[f];
        int k = f >> 5, c4 = f & 31;
        Bs4[f] = Bg[k * 128 + h * 32 + c4];
    }
    __syncthreads();

    int tx = tid & 15, ty = tid >> 4;
    int mo = ty * 8, no = tx * 8;
    float acc[8][8];
    #pragma unroll
    for (int a = 0; a < 8; a++)
        #pragma unroll
        for (int b = 0; b < 8; b++) acc[a][b] = 0.f;

    for (int k = 0; k < 128; k += 4) {
        float4 a4[8], b0[4], b1[4];
        #pragma unroll
        for (int mi = 0; mi < 8; mi++) a4[mi] = *(const float4*)(As + (mo + mi) * 128 + k);
        #pragma unroll
        for (int kk = 0; kk < 4; kk++) {
            b0[kk] = *(const float4*)(Bs + (k + kk) * 128 + no);
            b1[kk] = *(const float4*)(Bs + (k + kk) * 128 + no + 4);
        }
        #pragma unroll
        for (int mi = 0; mi < 8; mi++) {
            #pragma unroll
            for (int kk = 0; kk < 4; kk++) {
                float a = (kk == 0) ? a4[mi].x : (kk == 1) ? a4[mi].y : (kk == 2) ? a4[mi].z : a4[mi].w;
                acc[mi][0] = fmaf(a, b0[kk].x, acc[mi][0]);
                acc[mi][1] = fmaf(a, b0[kk].y, acc[mi][1]);
                acc[mi][2] = fmaf(a, b0[kk].z, acc[mi][2]);
                acc[mi][3] = fmaf(a, b0[kk].w, acc[mi][3]);
                acc[mi][4] = fmaf(a, b1[kk].x, acc[mi][4]);
                acc[mi][5] = fmaf(a, b1[kk].y, acc[mi][5]);
                acc[mi][6] = fmaf(a, b1[kk].z, acc[mi][6]);
                acc[mi][7] = fmaf(a, b1[kk].w, acc[mi][7]);
            }
        }
    }

    int sub = no >> 5, d0 = no & 31;
    float* dstbuf = (sub == 0) ? g_Q : (sub == 1) ? g_K : (sub == 2) ? g_V : g_G;
    float bgv[8];
    if (sub == 3) {
        #pragma unroll
        for (int ni = 0; ni < 8; ni++) bgv[ni] = bg[h * DH + d0 + ni];
    }
    #pragma unroll
    for (int mi = 0; mi < 8; mi++) {
        int m = m0 + mo + mi;
        int i = m / NN, j = m - i * NN;
        float* dst = dstbuf + ((size_t)(i * NH + h) * NN + j) * DH + d0;
        if (sub == 3) {
            #pragma unroll
            for (int ni = 0; ni < 8; ni++) {
                float val = acc[mi][ni] + bgv[ni];
                dst[ni] = 1.f / (1.f + __expf(-val));
            }
        } else {
            #pragma unroll
            for (int ni = 0; ni < 8; ni++) dst[ni] = acc[mi][ni];
        }
    }
}

// ---------------- K3: attention, one block per (row i, head h) ----------------
__global__ void __launch_bounds__(384) attn_kernel(const float* __restrict__ mask) {
    extern __shared__ float sm[];
    float* Ks = sm;                 // [384][32]
    float* Vs = sm + NN * DH;       // [384][32]
    int i = blockIdx.x, h = blockIdx.y;
    int tid = threadIdx.x;          // query index q
    size_t base = ((size_t)(i * NH + h)) * NN * DH;

    const float4* Kg = (const float4*)(g_K + base);
    const float4* Vg = (const float4*)(g_V + base);
    float4* Ks4 = (float4*)Ks;
    float4* Vs4 = (float4*)Vs;
    #pragma unroll
    for (int r = 0; r < 8; r++) {
        Ks4[tid + r * NN] = Kg[tid + r * NN];
        Vs4[tid + r * NN] = Vg[tid + r * NN];
    }
    float q[32];
    {
        const float4* Qg = (const float4*)(g_Q + base + (size_t)tid * DH);
        #pragma unroll
        for (int r = 0; r < 8; r++) ((float4*)q)[r] = Qg[r];
    }
    __syncthreads();

    float o[32];
    #pragma unroll
    for (int d = 0; d < 32; d++) o[d] = 0.f;
    float mrun = -1e30f, l = 0.f;
    const float* biasT = g_triBT + (size_t)h * M_TOT;   // [k][q]
    const float* mrow  = mask + (size_t)i * NN;

    for (int kc = 0; kc < NN; kc += 16) {
        float s[16];
        #pragma unroll
        for (int kk = 0; kk < 16; kk++) {
            const float4* krow = (const float4*)(Ks + (kc + kk) * DH);
            float acc = 0.f;
            #pragma unroll
            for (int d4 = 0; d4 < 8; d4++) {
                float4 k4 = krow[d4];
                acc = fmaf(q[d4*4+0], k4.x, acc);
                acc = fmaf(q[d4*4+1], k4.y, acc);
                acc = fmaf(q[d4*4+2], k4.z, acc);
                acc = fmaf(q[d4*4+3], k4.w, acc);
            }
            float mb = (__ldg(mrow + kc + kk) - 1.f) * 1e9f;
            s[kk] = acc + biasT[(size_t)(kc + kk) * NN + tid] + mb;
        }
        float cmax = s[0];
        #pragma unroll
        for (int kk = 1; kk < 16; kk++) cmax = fmaxf(cmax, s[kk]);
        float mnew = fmaxf(mrun, cmax);
        float corr = __expf(mrun - mnew);
        l *= corr;
        #pragma unroll
        for (int d = 0; d < 32; d++) o[d] *= corr;
        #pragma unroll
        for (int kk = 0; kk < 16; kk++) {
            float p = __expf(s[kk] - mnew);
            l += p;
            const float4* vrow = (const float4*)(Vs + (kc + kk) * DH);
            #pragma unroll
            for (int d4 = 0; d4 < 8; d4++) {
                float4 v4 = vrow[d4];
                o[d4*4+0] = fmaf(p, v4.x, o[d4*4+0]);
                o[d4*4+1] = fmaf(p, v4.y, o[d4*4+1]);
                o[d4*4+2] = fmaf(p, v4.z, o[d4*4+2]);
                o[d4*4+3] = fmaf(p, v4.w, o[d4*4+3]);
            }
        }
        mrun = mnew;
    }

    float inv = 1.f / l;
    const float4* Gg = (const float4*)(g_G + base + (size_t)tid * DH);
    float* ogp = g_OG + ((size_t)(i * NN + tid)) * CIN + h * DH;
    #pragma unroll
    for (int r = 0; r < 8; r++) {
        float4 g4 = Gg[r];
        float4 w;
        w.x = o[r*4+0] * inv * g4.x;
        w.y = o[r*4+1] * inv * g4.y;
        w.z = o[r*4+2] * inv * g4.z;
        w.w = o[r*4+3] * inv * g4.w;
        *(float4*)(ogp + r * 4) = w;
    }
}

// ---------------- K4: output GEMM + bias ----------------
__global__ void __launch_bounds__(256, 1) out_kernel(const float* __restrict__ bo,
                                                     float* __restrict__ out) {
    extern __shared__ float sm[];
    float* As = sm;
    float* Bs = sm + 128 * 128;
    int tid = threadIdx.x;
    int m0  = blockIdx.x * 128;

    const float4* Ag = (const float4*)(g_OG + (size_t)m0 * CIN);
    const float4* Bg = (const float4*)g_Bout;
    float4* As4 = (float4*)As;
    float4* Bs4 = (float4*)Bs;
    #pragma unroll
    for (int r = 0; r < 16; r++) {
        int f = tid + r * 256;
        As4[f] = Ag[f];
        Bs4[f] = Bg[f];
    }
    __syncthreads();

    int tx = tid & 15, ty = tid >> 4;
    int mo = ty * 8, no = tx * 8;
    float acc[8][8];
    #pragma unroll
    for (int a = 0; a < 8; a++)
        #pragma unroll
        for (int b = 0; b < 8; b++) acc[a][b] = 0.f;

    for (int k = 0; k < 128; k += 4) {
        float4 a4[8], b0[4], b1[4];
        #pragma unroll
        for (int mi = 0; mi < 8; mi++) a4[mi] = *(const float4*)(As + (mo + mi) * 128 + k);
        #pragma unroll
        for (int kk = 0; kk < 4; kk++) {
            b0[kk] = *(const float4*)(Bs + (k + kk) * 128 + no);
            b1[kk] = *(const float4*)(Bs + (k + kk) * 128 + no + 4);
        }
        #pragma unroll
        for (int mi = 0; mi < 8; mi++) {
            #pragma unroll
            for (int kk = 0; kk < 4; kk++) {
                float a = (kk == 0) ? a4[mi].x : (kk == 1) ? a4[mi].y : (kk == 2) ? a4[mi].z : a4[mi].w;
                acc[mi][0] = fmaf(a, b0[kk].x, acc[mi][0]);
                acc[mi][1] = fmaf(a, b0[kk].y, acc[mi][1]);
                acc[mi][2] = fmaf(a, b0[kk].z, acc[mi][2]);
                acc[mi][3] = fmaf(a, b0[kk].w, acc[mi][3]);
                acc[mi][4] = fmaf(a, b1[kk].x, acc[mi][4]);
                acc[mi][5] = fmaf(a, b1[kk].y, acc[mi][5]);
                acc[mi][6] = fmaf(a, b1[kk].z, acc[mi][6]);
                acc[mi][7] = fmaf(a, b1[kk].w, acc[mi][7]);
            }
        }
    }

    float bov[8];
    #pragma unroll
    for (int ni = 0; ni < 8; ni++) bov[ni] = bo[no + ni];
    #pragma unroll
    for (int mi = 0; mi < 8; mi++) {
        int m = m0 + mo + mi;
        float* dst = out + (size_t)m * CIN + no;
        float4 w0, w1;
        w0.x = acc[mi][0] + bov[0]; w0.y = acc[mi][1] + bov[1];
        w0.z = acc[mi][2] + bov[2]; w0.w = acc[mi][3] + bov[3];
        w1.x = acc[mi][4] + bov[4]; w1.y = acc[mi][5] + bov[5];
        w1.z = acc[mi][6] + bov[6]; w1.w = acc[mi][7] + bov[7];
        *(float4*)dst = w0;
        *(float4*)(dst + 4) = w1;
    }
}

// ---------------- launch ----------------
extern "C" void kernel_launch(void* const* d_in, const int* in_sizes, int n_in,
                              void* d_out, int out_size) {
    const float* x     = (const float*)d_in[0];
    const float* mask  = (const float*)d_in[1];
    const float* gamma = (const float*)d_in[2];
    const float* beta  = (const float*)d_in[3];
    const float* wbias = (const float*)d_in[4];
    const float* wq    = (const float*)d_in[5];
    const float* wk    = (const float*)d_in[6];
    const float* wv    = (const float*)d_in[7];
    const float* wg    = (const float*)d_in[8];
    const float* bg    = (const float*)d_in[9];
    const float* wo    = (const float*)d_in[10];
    const float* bo    = (const float*)d_in[11];
    float* out = (float*)d_out;

    cudaFuncSetAttribute(proj_kernel, cudaFuncAttributeMaxDynamicSharedMemorySize, 131072);
    cudaFuncSetAttribute(out_kernel,  cudaFuncAttributeMaxDynamicSharedMemorySize, 131072);
    cudaFuncSetAttribute(attn_kernel, cudaFuncAttributeMaxDynamicSharedMemorySize, 98304);

    pack_kernel<<<256, 256>>>(wq, wk, wv, wg, wo);
    ln_kernel<<<M_TOT / 8, 256>>>(x, gamma, beta, wbias);
    proj_kernel<<<dim3(M_TOT / 128, NH), 256, 131072>>>(bg);
    attn_kernel<<<dim3(NN, NH), NN, 98304>>>(mask);
    out_kernel<<<M_TOT / 128, 256, 131072>>>(bo, out);
}

// round 3
// speedup vs baseline: 1.3350x; 1.3350x over previous
#include <cuda_runtime.h>
#include <stdint.h>
#include <math.h>

#define NN 384
#define CIN 128
#define DH 32
#define NH 4
#define M_TOT (NN*NN)   // 147456

#define PAD_A 132   // fp32 smem row stride for A tiles (conflict-free mma frag loads)
#define PAD_B 136   // fp32 smem row stride for B tiles

// ---------------- scratch (no allocations allowed) ----------------
__device__ float g_xn[(size_t)M_TOT*CIN];      // layernormed x (tf32-rounded), [m][c]
__device__ float g_triBT[(size_t)NH*M_TOT];    // triangle bias TRANSPOSED: [h][k][q]
__device__ float g_Q[(size_t)M_TOT*CIN];       // [i][h][j][d]
__device__ float g_K[(size_t)M_TOT*CIN];
__device__ float g_V[(size_t)M_TOT*CIN];
__device__ float g_G[(size_t)M_TOT*CIN];       // sigmoid gate, [i][h][j][d]
__device__ float g_OG[(size_t)M_TOT*CIN];      // gated attention out, [m][h*32+d]
__device__ float g_Bqkvg[CIN*512];             // packed weights [k][n] (tf32-rounded)
__device__ float g_Bout[CIN*CIN];              // wo transposed [k][c] (tf32-rounded)

__device__ __forceinline__ float tf32r(float x) {
    uint32_t r;
    asm("cvt.rna.tf32.f32 %0, %1;" : "=r"(r) : "f"(x));
    return __uint_as_float(r);
}

// ---------------- K0: pack weights (tf32-rounded) ----------------
__global__ void pack_kernel(const float* __restrict__ wq, const float* __restrict__ wk,
                            const float* __restrict__ wv, const float* __restrict__ wg,
                            const float* __restrict__ wo) {
    int idx = blockIdx.x * 256 + threadIdx.x;
    if (idx < CIN * 512) {
        int k = idx >> 9, n = idx & 511;
        int h = n >> 7, t = n & 127, sub = t >> 5, d = t & 31;
        const float* w = (sub == 0) ? wq : (sub == 1) ? wk : (sub == 2) ? wv : wg;
        float val = w[(h * DH + d) * CIN + k];
        if (sub == 0) val *= 0.17677669529663687f;   // 1/sqrt(32)
        g_Bqkvg[idx] = tf32r(val);
    }
    if (idx < CIN * CIN) {
        int k = idx >> 7, c = idx & 127;
        g_Bout[idx] = tf32r(wo[c * CIN + k]);
    }
}

// ---------------- K1: LayerNorm + triangle bias ----------------
__global__ void __launch_bounds__(256) ln_kernel(const float* __restrict__ x,
                                                 const float* __restrict__ gamma,
                                                 const float* __restrict__ beta,
                                                 const float* __restrict__ wbias) {
    int wid = threadIdx.x >> 5, lane = threadIdx.x & 31;
    int p = blockIdx.x * 8 + wid;
    const float4 v = ((const float4*)(x + (size_t)p * CIN))[lane];
    float s  = v.x + v.y + v.z + v.w;
    float sq = v.x*v.x + v.y*v.y + v.z*v.z + v.w*v.w;
    #pragma unroll
    for (int o = 16; o; o >>= 1) {
        s  += __shfl_xor_sync(~0u, s,  o);
        sq += __shfl_xor_sync(~0u, sq, o);
    }
    float mu   = s * (1.f / 128.f);
    float var  = sq * (1.f / 128.f) - mu * mu;
    float rstd = rsqrtf(var + 1e-5f);
    float4 g4 = ((const float4*)gamma)[lane];
    float4 b4 = ((const float4*)beta)[lane];
    float4 xn;
    xn.x = (v.x - mu) * rstd * g4.x + b4.x;
    xn.y = (v.y - mu) * rstd * g4.y + b4.y;
    xn.z = (v.z - mu) * rstd * g4.z + b4.z;
    xn.w = (v.w - mu) * rstd * g4.w + b4.w;

    // triangle bias from full-precision xn
    int i = p / NN, j = p - i * NN;
    #pragma unroll
    for (int h = 0; h < NH; h++) {
        float4 w4 = ((const float4*)(wbias + h * CIN))[lane];
        float d = xn.x*w4.x + xn.y*w4.y + xn.z*w4.z + xn.w*w4.w;
        #pragma unroll
        for (int o = 16; o; o >>= 1) d += __shfl_xor_sync(~0u, d, o);
        if (lane == 0) g_triBT[(size_t)h * M_TOT + j * NN + i] = d;  // [h][k=j][q=i]
    }

    // store tf32-rounded xn for the tensor-core GEMM
    float4 xr;
    xr.x = tf32r(xn.x); xr.y = tf32r(xn.y); xr.z = tf32r(xn.z); xr.w = tf32r(xn.w);
    ((float4*)(g_xn + (size_t)p * CIN))[lane] = xr;
}

// ---------------- K2: projection GEMM via mma.sync tf32 ----------------
// grid: (NH, M_TOT/128). blockIdx.x = head (consecutive blocks share A tile via L2).
__global__ void __launch_bounds__(256, 1) proj_mma_kernel(const float* __restrict__ bg) {
    extern __shared__ float sm[];
    float* As = sm;                    // [128][PAD_A]
    float* Bs = sm + 128 * PAD_A;      // [128][PAD_B]
    int tid = threadIdx.x;
    int h   = blockIdx.x;
    int m0  = blockIdx.y * 128;

    const float4* Ag = (const float4*)(g_xn + (size_t)m0 * CIN);
    const float4* Bg = (const float4*)g_Bqkvg;   // [128 k][128 float4]
    #pragma unroll
    for (int r = 0; r < 16; r++) {
        int f = tid + r * 256;
        int row = f >> 5, c4 = f & 31;
        *(float4*)(As + row * PAD_A + c4 * 4) = Ag[f];
        *(float4*)(Bs + row * PAD_B + c4 * 4) = Bg[row * 128 + h * 32 + c4];
    }
    __syncthreads();

    int warp = tid >> 5, lane = tid & 31;
    int wm = (warp >> 1) * 32;   // 4 warps in M
    int wn = (warp & 1) * 64;    // 2 warps in N
    int g  = lane >> 2, tg = lane & 3;

    float c[2][8][4];
    #pragma unroll
    for (int a = 0; a < 2; a++)
        #pragma unroll
        for (int b = 0; b < 8; b++)
            #pragma unroll
            for (int e = 0; e < 4; e++) c[a][b][e] = 0.f;

    for (int k0 = 0; k0 < 128; k0 += 8) {
        uint32_t a[2][4];
        #pragma unroll
        for (int mt = 0; mt < 2; mt++) {
            const float* ap = As + (wm + mt * 16 + g) * PAD_A + k0 + tg;
            a[mt][0] = __float_as_uint(ap[0]);
            a[mt][1] = __float_as_uint(ap[8 * PAD_A]);
            a[mt][2] = __float_as_uint(ap[4]);
            a[mt][3] = __float_as_uint(ap[8 * PAD_A + 4]);
        }
        #pragma unroll
        for (int nt = 0; nt < 8; nt++) {
            const float* bp = Bs + (k0 + tg) * PAD_B + wn + nt * 8 + g;
            uint32_t b0 = __float_as_uint(bp[0]);
            uint32_t b1 = __float_as_uint(bp[4 * PAD_B]);
            #pragma unroll
            for (int mt = 0; mt < 2; mt++) {
                asm volatile("mma.sync.aligned.m16n8k8.row.col.f32.tf32.tf32.f32 "
                    "{%0,%1,%2,%3}, {%4,%5,%6,%7}, {%8,%9}, {%0,%1,%2,%3};"
                    : "+f"(c[mt][nt][0]), "+f"(c[mt][nt][1]),
                      "+f"(c[mt][nt][2]), "+f"(c[mt][nt][3])
                    : "r"(a[mt][0]), "r"(a[mt][1]), "r"(a[mt][2]), "r"(a[mt][3]),
                      "r"(b0), "r"(b1));
            }
        }
    }

    // epilogue: scatter into Q/K/V/G with [i][h][j][d] layout
    #pragma unroll
    for (int nt = 0; nt < 8; nt++) {
        int n = wn + nt * 8 + 2 * tg;      // col within this head's 128
        int sub = n >> 5, d0 = n & 31;
        float* dstbuf = (sub == 0) ? g_Q : (sub == 1) ? g_K : (sub == 2) ? g_V : g_G;
        float bg0 = 0.f, bg1 = 0.f;
        if (sub == 3) { bg0 = bg[h * DH + d0]; bg1 = bg[h * DH + d0 + 1]; }
        #pragma unroll
        for (int mt = 0; mt < 2; mt++) {
            #pragma unroll
            for (int rr = 0; rr < 2; rr++) {
                int m = m0 + wm + mt * 16 + g + rr * 8;
                int i = m / NN, j = m - i * NN;
                float v0 = c[mt][nt][rr * 2 + 0];
                float v1 = c[mt][nt][rr * 2 + 1];
                if (sub == 3) {
                    v0 = 1.f / (1.f + __expf(-(v0 + bg0)));
                    v1 = 1.f / (1.f + __expf(-(v1 + bg1)));
                }
                float* dst = dstbuf + ((size_t)(i * NH + h) * NN + j) * DH + d0;
                *(float2*)dst = make_float2(v0, v1);
            }
        }
    }
}

// ---------------- K3: attention, one block per (row i, head h) ----------------
__global__ void __launch_bounds__(384) attn_kernel(const float* __restrict__ mask) {
    extern __shared__ float sm[];
    float* Ks = sm;                 // [384][32]
    float* Vs = sm + NN * DH;       // [384][32]
    int i = blockIdx.x, h = blockIdx.y;
    int tid = threadIdx.x;          // query index q
    size_t base = ((size_t)(i * NH + h)) * NN * DH;

    const float4* Kg = (const float4*)(g_K + base);
    const float4* Vg = (const float4*)(g_V + base);
    float4* Ks4 = (float4*)Ks;
    float4* Vs4 = (float4*)Vs;
    #pragma unroll
    for (int r = 0; r < 8; r++) {
        Ks4[tid + r * NN] = Kg[tid + r * NN];
        Vs4[tid + r * NN] = Vg[tid + r * NN];
    }
    float q[32];
    {
        const float4* Qg = (const float4*)(g_Q + base + (size_t)tid * DH);
        #pragma unroll
        for (int r = 0; r < 8; r++) ((float4*)q)[r] = Qg[r];
    }
    __syncthreads();

    float o[32];
    #pragma unroll
    for (int d = 0; d < 32; d++) o[d] = 0.f;
    float mrun = -1e30f, l = 0.f;
    const float* biasT = g_triBT + (size_t)h * M_TOT;   // [k][q]
    const float* mrow  = mask + (size_t)i * NN;

    for (int kc = 0; kc < NN; kc += 16) {
        float s[16];
        #pragma unroll
        for (int kk = 0; kk < 16; kk++) {
            const float4* krow = (const float4*)(Ks + (kc + kk) * DH);
            float acc = 0.f;
            #pragma unroll
            for (int d4 = 0; d4 < 8; d4++) {
                float4 k4 = krow[d4];
                acc = fmaf(q[d4*4+0], k4.x, acc);
                acc = fmaf(q[d4*4+1], k4.y, acc);
                acc = fmaf(q[d4*4+2], k4.z, acc);
                acc = fmaf(q[d4*4+3], k4.w, acc);
            }
            float mb = (__ldg(mrow + kc + kk) - 1.f) * 1e9f;
            s[kk] = acc + biasT[(size_t)(kc + kk) * NN + tid] + mb;
        }
        float cmax = s[0];
        #pragma unroll
        for (int kk = 1; kk < 16; kk++) cmax = fmaxf(cmax, s[kk]);
        float mnew = fmaxf(mrun, cmax);
        float corr = __expf(mrun - mnew);
        l *= corr;
        #pragma unroll
        for (int d = 0; d < 32; d++) o[d] *= corr;
        #pragma unroll
        for (int kk = 0; kk < 16; kk++) {
            float p = __expf(s[kk] - mnew);
            l += p;
            const float4* vrow = (const float4*)(Vs + (kc + kk) * DH);
            #pragma unroll
            for (int d4 = 0; d4 < 8; d4++) {
                float4 v4 = vrow[d4];
                o[d4*4+0] = fmaf(p, v4.x, o[d4*4+0]);
                o[d4*4+1] = fmaf(p, v4.y, o[d4*4+1]);
                o[d4*4+2] = fmaf(p, v4.z, o[d4*4+2]);
                o[d4*4+3] = fmaf(p, v4.w, o[d4*4+3]);
            }
        }
        mrun = mnew;
    }

    float inv = 1.f / l;
    const float4* Gg = (const float4*)(g_G + base + (size_t)tid * DH);
    float* ogp = g_OG + ((size_t)(i * NN + tid)) * CIN + h * DH;
    #pragma unroll
    for (int r = 0; r < 8; r++) {
        float4 g4 = Gg[r];
        float4 w;
        w.x = o[r*4+0] * inv * g4.x;
        w.y = o[r*4+1] * inv * g4.y;
        w.z = o[r*4+2] * inv * g4.z;
        w.w = o[r*4+3] * inv * g4.w;
        *(float4*)(ogp + r * 4) = w;
    }
}

// ---------------- K4: output GEMM via mma.sync tf32 ----------------
__global__ void __launch_bounds__(256, 1) out_mma_kernel(const float* __restrict__ bo,
                                                         float* __restrict__ out) {
    extern __shared__ float sm[];
    float* As = sm;
    float* Bs = sm + 128 * PAD_A;
    int tid = threadIdx.x;
    int m0  = blockIdx.x * 128;

    const float4* Ag = (const float4*)(g_OG + (size_t)m0 * CIN);
    const float4* Bg = (const float4*)g_Bout;
    #pragma unroll
    for (int r = 0; r < 16; r++) {
        int f = tid + r * 256;
        int row = f >> 5, c4 = f & 31;
        float4 av = Ag[f];
        // round attention output to tf32 for consistent mma behavior
        av.x = tf32r(av.x); av.y = tf32r(av.y); av.z = tf32r(av.z); av.w = tf32r(av.w);
        *(float4*)(As + row * PAD_A + c4 * 4) = av;
        *(float4*)(Bs + row * PAD_B + c4 * 4) = Bg[f];
    }
    __syncthreads();

    int warp = tid >> 5, lane = tid & 31;
    int wm = (warp >> 1) * 32;
    int wn = (warp & 1) * 64;
    int g  = lane >> 2, tg = lane & 3;

    float c[2][8][4];
    #pragma unroll
    for (int a = 0; a < 2; a++)
        #pragma unroll
        for (int b = 0; b < 8; b++)
            #pragma unroll
            for (int e = 0; e < 4; e++) c[a][b][e] = 0.f;

    for (int k0 = 0; k0 < 128; k0 += 8) {
        uint32_t a[2][4];
        #pragma unroll
        for (int mt = 0; mt < 2; mt++) {
            const float* ap = As + (wm + mt * 16 + g) * PAD_A + k0 + tg;
            a[mt][0] = __float_as_uint(ap[0]);
            a[mt][1] = __float_as_uint(ap[8 * PAD_A]);
            a[mt][2] = __float_as_uint(ap[4]);
            a[mt][3] = __float_as_uint(ap[8 * PAD_A + 4]);
        }
        #pragma unroll
        for (int nt = 0; nt < 8; nt++) {
            const float* bp = Bs + (k0 + tg) * PAD_B + wn + nt * 8 + g;
            uint32_t b0 = __float_as_uint(bp[0]);
            uint32_t b1 = __float_as_uint(bp[4 * PAD_B]);
            #pragma unroll
            for (int mt = 0; mt < 2; mt++) {
                asm volatile("mma.sync.aligned.m16n8k8.row.col.f32.tf32.tf32.f32 "
                    "{%0,%1,%2,%3}, {%4,%5,%6,%7}, {%8,%9}, {%0,%1,%2,%3};"
                    : "+f"(c[mt][nt][0]), "+f"(c[mt][nt][1]),
                      "+f"(c[mt][nt][2]), "+f"(c[mt][nt][3])
                    : "r"(a[mt][0]), "r"(a[mt][1]), "r"(a[mt][2]), "r"(a[mt][3]),
                      "r"(b0), "r"(b1));
            }
        }
    }

    #pragma unroll
    for (int nt = 0; nt < 8; nt++) {
        int n = wn + nt * 8 + 2 * tg;
        float bo0 = bo[n], bo1 = bo[n + 1];
        #pragma unroll
        for (int mt = 0; mt < 2; mt++) {
            #pragma unroll
            for (int rr = 0; rr < 2; rr++) {
                int m = m0 + wm + mt * 16 + g + rr * 8;
                float* dst = out + (size_t)m * CIN + n;
                *(float2*)dst = make_float2(c[mt][nt][rr*2+0] + bo0,
                                            c[mt][nt][rr*2+1] + bo1);
            }
        }
    }
}

// ---------------- launch ----------------
extern "C" void kernel_launch(void* const* d_in, const int* in_sizes, int n_in,
                              void* d_out, int out_size) {
    const float* x     = (const float*)d_in[0];
    const float* mask  = (const float*)d_in[1];
    const float* gamma = (const float*)d_in[2];
    const float* beta  = (const float*)d_in[3];
    const float* wbias = (const float*)d_in[4];
    const float* wq    = (const float*)d_in[5];
    const float* wk    = (const float*)d_in[6];
    const float* wv    = (const float*)d_in[7];
    const float* wg    = (const float*)d_in[8];
    const float* bg    = (const float*)d_in[9];
    const float* wo    = (const float*)d_in[10];
    const float* bo    = (const float*)d_in[11];
    float* out = (float*)d_out;

    const int smem_gemm = 128 * PAD_A * 4 + 128 * PAD_B * 4;  // 137216
    cudaFuncSetAttribute(proj_mma_kernel, cudaFuncAttributeMaxDynamicSharedMemorySize, smem_gemm);
    cudaFuncSetAttribute(out_mma_kernel,  cudaFuncAttributeMaxDynamicSharedMemorySize, smem_gemm);
    cudaFuncSetAttribute(attn_kernel, cudaFuncAttributeMaxDynamicSharedMemorySize, 98304);

    pack_kernel<<<256, 256>>>(wq, wk, wv, wg, wo);
    ln_kernel<<<M_TOT / 8, 256>>>(x, gamma, beta, wbias);
    proj_mma_kernel<<<dim3(NH, M_TOT / 128), 256, smem_gemm>>>(bg);
    attn_kernel<<<dim3(NN, NH), NN, 98304>>>(mask);
    out_mma_kernel<<<M_TOT / 128, 256, smem_gemm>>>(bo, out);
}